// round 1
// baseline (speedup 1.0000x reference)
#include <cuda_runtime.h>
#include <math.h>

// ---------------- problem constants ----------------
#define BATCH 32
#define HH    64
#define WW    64
#define CC    192
#define NHEAD 6
#define HDIM  32
#define WS    8
#define NTOK  131072          // B*H*W = 32*64*64
#define HID   768

// ---------------- scratch (device globals; no runtime alloc) ----------------
__device__ float g_hln [NTOK * CC];        // LN1 output, window layout [2048,64,192]
__device__ float g_kv  [NTOK * 2 * CC];    // KV, window layout [2048*64, 384]
__device__ float g_obuf[NTOK * CC];        // attention output, window layout
__device__ float g_ybuf[NTOK * CC];        // y = x + proj(o), pixel layout
__device__ float g_h2a [NTOK * CC];        // LN2 output, pixel layout
__device__ float g_mid [NTOK * HID];       // gelu(fc1) output, pixel layout

// window-layout row -> pixel-layout row
__device__ __forceinline__ int win_to_pix(int r) {
    int w = r >> 6, n = r & 63;
    int b = w >> 6, wy = (w >> 3) & 7, wx = w & 7;
    int iy = n >> 3, ix = n & 7;
    return (b << 12) | (((wy << 3) + iy) << 6) | ((wx << 3) + ix);
}

// ---------------- LayerNorm (one warp per token) ----------------
// WINDOWED: read input at pixel index (mapped), write at window-layout row.
// else:     read and write at the same (pixel) row.
template<bool WINDOWED>
__global__ void ln_kernel(const float* __restrict__ in, const float* __restrict__ gamma,
                          const float* __restrict__ beta, float* __restrict__ out)
{
    int warp = threadIdx.x >> 5, lane = threadIdx.x & 31;
    int t = blockIdx.x * 8 + warp;
    int rd = WINDOWED ? win_to_pix(t) : t;
    const float* row = in + (size_t)rd * CC;
    float v[6];
    float s = 0.f, sq = 0.f;
#pragma unroll
    for (int k = 0; k < 6; k++) {
        v[k] = row[lane + 32 * k];
        s += v[k]; sq += v[k] * v[k];
    }
#pragma unroll
    for (int o = 16; o; o >>= 1) {
        s  += __shfl_xor_sync(0xffffffffu, s,  o);
        sq += __shfl_xor_sync(0xffffffffu, sq, o);
    }
    float mean = s * (1.f / CC);
    float var  = sq * (1.f / CC) - mean * mean;
    float rstd = rsqrtf(var + 1e-5f);
    float* orow = out + (size_t)t * CC;
#pragma unroll
    for (int k = 0; k < 6; k++) {
        int c = lane + 32 * k;
        orow[c] = (v[k] - mean) * rstd * gamma[c] + beta[c];
    }
}

// ---------------- tiled fp32 GEMM: C = A[M,K] @ B[K,N] + epilogue ----------------
// 64x64 block tile, 256 threads, 4x4 per-thread tile, BK=16.
// MODE 0: + bias, plain store                       (KV GEMM)
// MODE 1: + bias, + resid[pix], store at pix        (proj + residual, window->pixel)
// MODE 2: + bias, exact GELU                        (fc1)
// MODE 3: + bias, + resid[row], store               (fc2 + residual)
template<int MODE>
__global__ void gemm_kernel(const float* __restrict__ A, const float* __restrict__ Bm,
                            const float* __restrict__ bias, const float* __restrict__ resid,
                            float* __restrict__ Cout, int M, int N, int K)
{
    __shared__ float As[16][64];   // As[k][m]
    __shared__ float Bs[16][64];   // Bs[k][n]
    int tid = threadIdx.x;
    int tx = tid & 15, ty = tid >> 4;
    int n0 = blockIdx.x * 64, m0 = blockIdx.y * 64;
    int a_row = tid >> 2, a_c4 = tid & 3;     // 64 rows x 4 float4 columns
    int b_row = tid >> 4, b_c4 = tid & 15;    // 16 rows x 16 float4 columns

    float acc[4][4];
#pragma unroll
    for (int i = 0; i < 4; i++)
#pragma unroll
        for (int j = 0; j < 4; j++) acc[i][j] = 0.f;

    for (int kt = 0; kt < K; kt += 16) {
        float4 av = *(const float4*)(A + (size_t)(m0 + a_row) * K + kt + a_c4 * 4);
        As[a_c4 * 4 + 0][a_row] = av.x;
        As[a_c4 * 4 + 1][a_row] = av.y;
        As[a_c4 * 4 + 2][a_row] = av.z;
        As[a_c4 * 4 + 3][a_row] = av.w;
        float4 bv = *(const float4*)(Bm + (size_t)(kt + b_row) * N + n0 + b_c4 * 4);
        *(float4*)&Bs[b_row][b_c4 * 4] = bv;
        __syncthreads();
#pragma unroll
        for (int kk = 0; kk < 16; kk++) {
            float4 a4 = *(const float4*)&As[kk][ty * 4];
            float4 b4 = *(const float4*)&Bs[kk][tx * 4];
            float ar[4] = {a4.x, a4.y, a4.z, a4.w};
            float br[4] = {b4.x, b4.y, b4.z, b4.w};
#pragma unroll
            for (int i = 0; i < 4; i++)
#pragma unroll
                for (int j = 0; j < 4; j++) acc[i][j] += ar[i] * br[j];
        }
        __syncthreads();
    }

#pragma unroll
    for (int i = 0; i < 4; i++) {
        int r = m0 + ty * 4 + i;
#pragma unroll
        for (int j = 0; j < 4; j++) {
            int c = n0 + tx * 4 + j;
            float v = acc[i][j] + bias[c];
            if (MODE == 0) {
                Cout[(size_t)r * N + c] = v;
            } else if (MODE == 1) {
                int pix = win_to_pix(r);
                Cout[(size_t)pix * CC + c] = v + resid[(size_t)pix * CC + c];
            } else if (MODE == 2) {
                Cout[(size_t)r * N + c] = 0.5f * v * (1.f + erff(v * 0.70710678118654752f));
            } else {
                Cout[(size_t)r * N + c] = v + resid[(size_t)r * N + c];
            }
        }
    }
}

// ---------------- windowed attention with global query ----------------
// One block per (window, head), 64 threads (one per query token).
__global__ void attn_kernel(const float* __restrict__ kv, const float* __restrict__ qg,
                            const float* __restrict__ rpb, float* __restrict__ obuf)
{
    __shared__ float Ks[64][33];
    __shared__ float Vs[64][33];
    __shared__ float Ss[64][65];
    int w = blockIdx.x, h = blockIdx.y;
    int n = threadIdx.x;
    int b = w >> 6;

    const float* kvr = kv + (size_t)(w * 64 + n) * (2 * CC) + h * HDIM;
#pragma unroll
    for (int d = 0; d < HDIM; d++) {
        Ks[n][d] = kvr[d];
        Vs[n][d] = kvr[CC + d];
    }
    // q = q_global[b, n, h, :] * scale
    float q[HDIM];
    const float* qr = qg + (size_t)((b * 64 + n) * NHEAD + h) * HDIM;
    const float scale = 0.17677669529663689f;  // 1/sqrt(32)
#pragma unroll
    for (int d = 0; d < HDIM; d++) q[d] = qr[d] * scale;
    __syncthreads();

    int iy = n >> 3, ix = n & 7;
    float mx = -1e30f;
    for (int m = 0; m < 64; m++) {
        float s = 0.f;
#pragma unroll
        for (int d = 0; d < HDIM; d++) s += q[d] * Ks[m][d];
        int idx = (iy - (m >> 3) + 7) * 15 + (ix - (m & 7) + 7);
        s += rpb[idx * NHEAD + h];
        Ss[n][m] = s;
        mx = fmaxf(mx, s);
    }
    float sum = 0.f;
    for (int m = 0; m < 64; m++) {
        float e = __expf(Ss[n][m] - mx);
        Ss[n][m] = e;
        sum += e;
    }
    float inv = 1.f / sum;

    float o[HDIM];
#pragma unroll
    for (int d = 0; d < HDIM; d++) o[d] = 0.f;
    for (int m = 0; m < 64; m++) {
        float p = Ss[n][m];
#pragma unroll
        for (int d = 0; d < HDIM; d++) o[d] += p * Vs[m][d];
    }
    float* orow = obuf + (size_t)(w * 64 + n) * CC + h * HDIM;
#pragma unroll
    for (int d = 0; d < HDIM; d++) orow[d] = o[d] * inv;
}

// ---------------- launch ----------------
extern "C" void kernel_launch(void* const* d_in, const int* in_sizes, int n_in,
                              void* d_out, int out_size)
{
    const float* x     = (const float*)d_in[0];
    const float* qg    = (const float*)d_in[1];
    const float* n1g   = (const float*)d_in[2];
    const float* n1b   = (const float*)d_in[3];
    const float* qkvw  = (const float*)d_in[4];
    const float* qkvb  = (const float*)d_in[5];
    const float* rpb   = (const float*)d_in[6];
    const float* projw = (const float*)d_in[7];
    const float* projb = (const float*)d_in[8];
    const float* n2g   = (const float*)d_in[9];
    const float* n2b   = (const float*)d_in[10];
    const float* fc1w  = (const float*)d_in[11];
    const float* fc1b  = (const float*)d_in[12];
    const float* fc2w  = (const float*)d_in[13];
    const float* fc2b  = (const float*)d_in[14];
    float* out = (float*)d_out;

    float *hln, *kvb, *ob, *yb, *h2a, *mid;
    cudaGetSymbolAddress((void**)&hln, g_hln);
    cudaGetSymbolAddress((void**)&kvb, g_kv);
    cudaGetSymbolAddress((void**)&ob,  g_obuf);
    cudaGetSymbolAddress((void**)&yb,  g_ybuf);
    cudaGetSymbolAddress((void**)&h2a, g_h2a);
    cudaGetSymbolAddress((void**)&mid, g_mid);

    // 1. LN1 + window partition
    ln_kernel<true><<<NTOK / 8, 256>>>(x, n1g, n1b, hln);
    // 2. KV = hln @ qkv_w + qkv_b          [131072, 384]
    gemm_kernel<0><<<dim3(384 / 64, NTOK / 64), 256>>>(hln, qkvw, qkvb, nullptr, kvb,
                                                       NTOK, 2 * CC, CC);
    // 3. windowed attention (global query + relative position bias)
    attn_kernel<<<dim3(2048, NHEAD), 64>>>(kvb, qg, rpb, ob);
    // 4. y = x + o @ proj_w + proj_b       (window -> pixel layout)
    gemm_kernel<1><<<dim3(CC / 64, NTOK / 64), 256>>>(ob, projw, projb, x, yb,
                                                      NTOK, CC, CC);
    // 5. LN2
    ln_kernel<false><<<NTOK / 8, 256>>>(yb, n2g, n2b, h2a);
    // 6. mid = gelu(h2a @ fc1_w + fc1_b)   [131072, 768]
    gemm_kernel<2><<<dim3(HID / 64, NTOK / 64), 256>>>(h2a, fc1w, fc1b, nullptr, mid,
                                                       NTOK, HID, CC);
    // 7. out = y + mid @ fc2_w + fc2_b
    gemm_kernel<3><<<dim3(CC / 64, NTOK / 64), 256>>>(mid, fc2w, fc2b, yb, out,
                                                      NTOK, CC, HID);
}

// round 5
// speedup vs baseline: 1.8658x; 1.8658x over previous
#include <cuda_runtime.h>
#include <cstdint>
#include <math.h>

// ---------------- problem constants ----------------
#define CC    192
#define NHEAD 6
#define HDIM  32
#define NTOK  131072          // B*H*W = 32*64*64
#define HID   768

// ---------------- scratch ----------------
__device__ float g_hln [NTOK * CC];
__device__ float g_kv  [NTOK * 2 * CC];
__device__ float g_obuf[NTOK * CC];
__device__ float g_ybuf[NTOK * CC];
__device__ float g_h2a [NTOK * CC];
__device__ float g_mid [NTOK * HID];

__device__ __forceinline__ int win_to_pix(int r) {
    int w = r >> 6, n = r & 63;
    int b = w >> 6, wy = (w >> 3) & 7, wx = w & 7;
    int iy = n >> 3, ix = n & 7;
    return (b << 12) | (((wy << 3) + iy) << 6) | ((wx << 3) + ix);
}

__device__ __forceinline__ uint32_t tf32r(float x) {
    uint32_t u;
    asm("cvt.rna.tf32.f32 %0, %1;" : "=r"(u) : "f"(x));
    return u;
}

__device__ __forceinline__ void mma_tf32(float* c, const uint32_t* a, const uint32_t* b) {
    asm volatile(
        "mma.sync.aligned.m16n8k8.row.col.f32.tf32.tf32.f32 "
        "{%0,%1,%2,%3}, {%4,%5,%6,%7}, {%8,%9}, {%0,%1,%2,%3};"
        : "+f"(c[0]), "+f"(c[1]), "+f"(c[2]), "+f"(c[3])
        : "r"(a[0]), "r"(a[1]), "r"(a[2]), "r"(a[3]), "r"(b[0]), "r"(b[1]));
}

// ---------------- smem layout (floats, STATIC — fits 48KB) ----------------
// As buffers: 128 rows x stride 20  (2 x 2560 floats)   BK=16
// Bs buffers: 16 rows  x stride 72  (2 x 1152 floats)
// Epilogue restage: 128 rows x stride 68 = 8704 floats (aliases everything)
#define AS_STRIDE 20
#define BS_STRIDE 72
#define AS_FLOATS 2560
#define BS_FLOATS 1152
#define SMEM_FLOATS 8704        // 34816 bytes, static

// ---------------- tf32 mma.sync GEMM: C[M,N] = A[M,K] @ B[K,N] + epilogue ----------------
// CTA tile 128x64, BK=16, 256 threads; warp grid 4(m) x 2(n), warp tile 32x32.
// MODE 0: +bias        MODE 1: +bias, +resid[pix], window->pixel remap
// MODE 2: +bias, GELU  MODE 3: +bias, +resid[row]
template<int MODE>
__global__ void __launch_bounds__(256)
mm_gemm(const float* __restrict__ A, const float* __restrict__ B,
        const float* __restrict__ bias, const float* __restrict__ resid,
        float* __restrict__ Cout, int M, int N, int K)
{
    __shared__ float smemf[SMEM_FLOATS];
    int tid = threadIdx.x;
    int wid = tid >> 5, lane = tid & 31;
    int wm = wid & 3, wn = wid >> 2;           // warp 32x32 tile at (wm*32, wn*32)
    int g = lane >> 2, t = lane & 3;           // mma fragment coords
    int n0 = blockIdx.x * 64, m0 = blockIdx.y * 128;

    // gmem load coords
    int a_row = tid >> 2, a_c4 = (tid & 3) * 4;    // 64 rows/iter, 2 iters
    int b_row = tid >> 4, b_c4 = (tid & 15) * 4;   // 16 rows, 1 iter

    float acc[2][4][4];
#pragma unroll
    for (int i = 0; i < 2; i++)
#pragma unroll
        for (int j = 0; j < 4; j++)
#pragma unroll
            for (int q = 0; q < 4; q++) acc[i][j][q] = 0.f;

    const int nch = K >> 4;

    // ---- preload chunk 0 into buffer 0 ----
    {
        float* As = smemf;
        float* Bs = smemf + 2 * AS_FLOATS;
#pragma unroll
        for (int it = 0; it < 2; it++) {
            int row = a_row + it * 64;
            float4 v = *(const float4*)(A + (size_t)(m0 + row) * K + a_c4);
            uint32_t* d = (uint32_t*)&As[row * AS_STRIDE + a_c4];
            d[0] = tf32r(v.x); d[1] = tf32r(v.y); d[2] = tf32r(v.z); d[3] = tf32r(v.w);
        }
        {
            float4 v = *(const float4*)(B + (size_t)b_row * N + n0 + b_c4);
            uint32_t* d = (uint32_t*)&Bs[b_row * BS_STRIDE + b_c4];
            d[0] = tf32r(v.x); d[1] = tf32r(v.y); d[2] = tf32r(v.z); d[3] = tf32r(v.w);
        }
    }
    __syncthreads();

    for (int c = 0; c < nch; c++) {
        int buf = c & 1;
        float* As = smemf + buf * AS_FLOATS;
        float* Bs = smemf + 2 * AS_FLOATS + buf * BS_FLOATS;

        // issue gmem loads for next chunk (latency overlapped with compute)
        float4 av[2], bv;
        if (c + 1 < nch) {
            int kc = (c + 1) * 16;
            const float* Ab = A + (size_t)m0 * K + kc;
#pragma unroll
            for (int it = 0; it < 2; it++)
                av[it] = *(const float4*)(Ab + (size_t)(a_row + it * 64) * K + a_c4);
            bv = *(const float4*)(B + (size_t)(kc + b_row) * N + n0 + b_c4);
        }

        // compute on current buffer
#pragma unroll
        for (int ks = 0; ks < 2; ks++) {
            uint32_t af[2][4], bf[4][2];
#pragma unroll
            for (int tm = 0; tm < 2; tm++) {
                int r0 = wm * 32 + tm * 16 + g;
                int k0 = ks * 8 + t;
                const uint32_t* Au = (const uint32_t*)As;
                af[tm][0] = Au[r0 * AS_STRIDE + k0];
                af[tm][1] = Au[(r0 + 8) * AS_STRIDE + k0];
                af[tm][2] = Au[r0 * AS_STRIDE + k0 + 4];
                af[tm][3] = Au[(r0 + 8) * AS_STRIDE + k0 + 4];
            }
#pragma unroll
            for (int tn = 0; tn < 4; tn++) {
                int col = wn * 32 + tn * 8 + g;
                int k0 = ks * 8 + t;
                const uint32_t* Bu = (const uint32_t*)Bs;
                bf[tn][0] = Bu[k0 * BS_STRIDE + col];
                bf[tn][1] = Bu[(k0 + 4) * BS_STRIDE + col];
            }
#pragma unroll
            for (int tm = 0; tm < 2; tm++)
#pragma unroll
                for (int tn = 0; tn < 4; tn++)
                    mma_tf32(acc[tm][tn], af[tm], bf[tn]);
        }

        // stage next chunk into the other buffer
        if (c + 1 < nch) {
            float* Asn = smemf + (buf ^ 1) * AS_FLOATS;
            float* Bsn = smemf + 2 * AS_FLOATS + (buf ^ 1) * BS_FLOATS;
#pragma unroll
            for (int it = 0; it < 2; it++) {
                int row = a_row + it * 64;
                uint32_t* d = (uint32_t*)&Asn[row * AS_STRIDE + a_c4];
                d[0] = tf32r(av[it].x); d[1] = tf32r(av[it].y);
                d[2] = tf32r(av[it].z); d[3] = tf32r(av[it].w);
            }
            {
                uint32_t* d = (uint32_t*)&Bsn[b_row * BS_STRIDE + b_c4];
                d[0] = tf32r(bv.x); d[1] = tf32r(bv.y);
                d[2] = tf32r(bv.z); d[3] = tf32r(bv.w);
            }
        }
        __syncthreads();
    }

    // ---- epilogue: regs -> smem restage (stride 68) -> coalesced STG ----
    float* Ss = smemf;
#pragma unroll
    for (int tm = 0; tm < 2; tm++) {
        int r0 = wm * 32 + tm * 16 + g;
#pragma unroll
        for (int tn = 0; tn < 4; tn++) {
            int col = wn * 32 + tn * 8 + 2 * t;
            *(float2*)&Ss[r0 * 68 + col]       = make_float2(acc[tm][tn][0], acc[tm][tn][1]);
            *(float2*)&Ss[(r0 + 8) * 68 + col] = make_float2(acc[tm][tn][2], acc[tm][tn][3]);
        }
    }
    __syncthreads();
#pragma unroll
    for (int it = 0; it < 8; it++) {
        int f = tid + it * 256;
        int row = f >> 4, c4 = (f & 15) * 4;
        float4 v = *(const float4*)&Ss[row * 68 + c4];
        int r = m0 + row, cl = n0 + c4;
        v.x += bias[cl]; v.y += bias[cl + 1]; v.z += bias[cl + 2]; v.w += bias[cl + 3];
        if (MODE == 2) {
            v.x = 0.5f * v.x * (1.f + erff(v.x * 0.70710678f));
            v.y = 0.5f * v.y * (1.f + erff(v.y * 0.70710678f));
            v.z = 0.5f * v.z * (1.f + erff(v.z * 0.70710678f));
            v.w = 0.5f * v.w * (1.f + erff(v.w * 0.70710678f));
        }
        if (MODE == 0 || MODE == 2) {
            *(float4*)(Cout + (size_t)r * N + cl) = v;
        } else if (MODE == 1) {
            int pix = win_to_pix(r);
            size_t o = (size_t)pix * N + cl;
            float4 rs = *(const float4*)(resid + o);
            v.x += rs.x; v.y += rs.y; v.z += rs.z; v.w += rs.w;
            *(float4*)(Cout + o) = v;
        } else {
            size_t o = (size_t)r * N + cl;
            float4 rs = *(const float4*)(resid + o);
            v.x += rs.x; v.y += rs.y; v.z += rs.z; v.w += rs.w;
            *(float4*)(Cout + o) = v;
        }
    }
}

// ---------------- LayerNorm (one warp per token) ----------------
template<bool WINDOWED>
__global__ void ln_kernel(const float* __restrict__ in, const float* __restrict__ gamma,
                          const float* __restrict__ beta, float* __restrict__ out)
{
    int warp = threadIdx.x >> 5, lane = threadIdx.x & 31;
    int tk = blockIdx.x * 8 + warp;
    int rd = WINDOWED ? win_to_pix(tk) : tk;
    const float* row = in + (size_t)rd * CC;
    float v[6];
    float s = 0.f, sq = 0.f;
#pragma unroll
    for (int k = 0; k < 6; k++) {
        v[k] = row[lane + 32 * k];
        s += v[k]; sq += v[k] * v[k];
    }
#pragma unroll
    for (int o = 16; o; o >>= 1) {
        s  += __shfl_xor_sync(0xffffffffu, s,  o);
        sq += __shfl_xor_sync(0xffffffffu, sq, o);
    }
    float mean = s * (1.f / CC);
    float var  = sq * (1.f / CC) - mean * mean;
    float rstd = rsqrtf(var + 1e-5f);
    float* orow = out + (size_t)tk * CC;
#pragma unroll
    for (int k = 0; k < 6; k++) {
        int c = lane + 32 * k;
        orow[c] = (v[k] - mean) * rstd * gamma[c] + beta[c];
    }
}

// ---------------- windowed attention (global query) ----------------
__global__ void attn_kernel(const float* __restrict__ kv, const float* __restrict__ qg,
                            const float* __restrict__ rpb, float* __restrict__ obuf)
{
    __shared__ float Ks[64][33];
    __shared__ float Vs[64][33];
    __shared__ float Ss[64][65];
    int w = blockIdx.x, h = blockIdx.y;
    int n = threadIdx.x;
    int b = w >> 6;

    const float* kvr = kv + (size_t)(w * 64 + n) * (2 * CC) + h * HDIM;
#pragma unroll
    for (int d = 0; d < HDIM; d++) {
        Ks[n][d] = kvr[d];
        Vs[n][d] = kvr[CC + d];
    }
    float q[HDIM];
    const float* qr = qg + (size_t)((b * 64 + n) * NHEAD + h) * HDIM;
    const float scale = 0.17677669529663689f;
#pragma unroll
    for (int d = 0; d < HDIM; d++) q[d] = qr[d] * scale;
    __syncthreads();

    int iy = n >> 3, ix = n & 7;
    float mx = -1e30f;
    for (int m = 0; m < 64; m++) {
        float s = 0.f;
#pragma unroll
        for (int d = 0; d < HDIM; d++) s += q[d] * Ks[m][d];
        int idx = (iy - (m >> 3) + 7) * 15 + (ix - (m & 7) + 7);
        s += rpb[idx * NHEAD + h];
        Ss[n][m] = s;
        mx = fmaxf(mx, s);
    }
    float sum = 0.f;
    for (int m = 0; m < 64; m++) {
        float e = __expf(Ss[n][m] - mx);
        Ss[n][m] = e;
        sum += e;
    }
    float inv = 1.f / sum;

    float o[HDIM];
#pragma unroll
    for (int d = 0; d < HDIM; d++) o[d] = 0.f;
    for (int m = 0; m < 64; m++) {
        float p = Ss[n][m];
#pragma unroll
        for (int d = 0; d < HDIM; d++) o[d] += p * Vs[m][d];
    }
    float* orow = obuf + (size_t)(w * 64 + n) * CC + h * HDIM;
#pragma unroll
    for (int d = 0; d < HDIM; d++) orow[d] = o[d] * inv;
}

// ---------------- launch ----------------
extern "C" void kernel_launch(void* const* d_in, const int* in_sizes, int n_in,
                              void* d_out, int out_size)
{
    const float* x     = (const float*)d_in[0];
    const float* qg    = (const float*)d_in[1];
    const float* n1g   = (const float*)d_in[2];
    const float* n1b   = (const float*)d_in[3];
    const float* qkvw  = (const float*)d_in[4];
    const float* qkvb  = (const float*)d_in[5];
    const float* rpb   = (const float*)d_in[6];
    const float* projw = (const float*)d_in[7];
    const float* projb = (const float*)d_in[8];
    const float* n2g   = (const float*)d_in[9];
    const float* n2b   = (const float*)d_in[10];
    const float* fc1w  = (const float*)d_in[11];
    const float* fc1b  = (const float*)d_in[12];
    const float* fc2w  = (const float*)d_in[13];
    const float* fc2b  = (const float*)d_in[14];
    float* out = (float*)d_out;

    float *hln, *kvb, *ob, *yb, *h2a, *mid;
    cudaGetSymbolAddress((void**)&hln, g_hln);
    cudaGetSymbolAddress((void**)&kvb, g_kv);
    cudaGetSymbolAddress((void**)&ob,  g_obuf);
    cudaGetSymbolAddress((void**)&yb,  g_ybuf);
    cudaGetSymbolAddress((void**)&h2a, g_h2a);
    cudaGetSymbolAddress((void**)&mid, g_mid);

    // 1. LN1 + window partition
    ln_kernel<true><<<NTOK / 8, 256>>>(x, n1g, n1b, hln);
    // 2. KV = hln @ qkv_w + qkv_b          [131072, 384]
    mm_gemm<0><<<dim3(384 / 64, NTOK / 128), 256>>>(hln, qkvw, qkvb, nullptr, kvb,
                                                    NTOK, 2 * CC, CC);
    // 3. windowed attention
    attn_kernel<<<dim3(2048, NHEAD), 64>>>(kvb, qg, rpb, ob);
    // 4. y = x + o @ proj_w + proj_b       (window -> pixel)
    mm_gemm<1><<<dim3(CC / 64, NTOK / 128), 256>>>(ob, projw, projb, x, yb,
                                                   NTOK, CC, CC);
    // 5. LN2
    ln_kernel<false><<<NTOK / 8, 256>>>(yb, n2g, n2b, h2a);
    // 6. mid = gelu(h2a @ fc1_w + fc1_b)   [131072, 768]
    mm_gemm<2><<<dim3(HID / 64, NTOK / 128), 256>>>(h2a, fc1w, fc1b, nullptr, mid,
                                                    NTOK, HID, CC);
    // 7. out = y + mid @ fc2_w + fc2_b
    mm_gemm<3><<<dim3(CC / 64, NTOK / 128), 256>>>(mid, fc2w, fc2b, yb, out,
                                                   NTOK, CC, HID);
}